// round 8
// baseline (speedup 1.0000x reference)
#include <cuda_runtime.h>

// Problem constants
#define B 32
#define S 2048
#define H 1024

// ---- split-softmax config ----
#define NSPLIT 16            // S-splits per batch
#define CH (S / NSPLIT)      // 128 rows per CTA
#define WARPS 4              // 128-thread CTAs
#define RPW (CH / WARPS)     // 32 rows per warp

// ---- q GEMV config ----
#define KSLICES 32
#define KCH (H / KSLICES)    // 32
#define BG 8

// Scratch (no cudaMalloc allowed)
__device__ float  g_qpart[KSLICES * B * H];          // 4 MB
__device__ float  g_q[B * H];                        // 128 KB
__device__ float4 g_pacc[B * NSPLIT * (H / 4)];      // 2 MB
__device__ float  g_ml[B * NSPLIT * 2];              // merged (M, L) per split

// ---------------------------------------------------------------------------
// Kernel 1: partial q[b,h] = sum_{k in slice} h_t[b,k] * W[k,h]
// grid (1, KSLICES=32, B/BG=4), 256 threads.
// ---------------------------------------------------------------------------
__global__ __launch_bounds__(256) void qpart_kernel(const float* __restrict__ h_t,
                                                    const float* __restrict__ W)
{
    __shared__ float hs[BG][KCH];
    const int tid = threadIdx.x;
    const int k0  = blockIdx.y * KCH;
    const int bg  = blockIdx.z;

    {   // BG*KCH = 256 floats, one per thread
        int j  = tid >> 5;
        int kk = tid & 31;
        hs[j][kk] = h_t[(bg * BG + j) * H + k0 + kk];
    }
    __syncthreads();

    float4 acc[BG];
    #pragma unroll
    for (int j = 0; j < BG; j++) acc[j] = make_float4(0.f, 0.f, 0.f, 0.f);

    const float4* wp = reinterpret_cast<const float4*>(W) + (size_t)k0 * 256 + tid;
    #pragma unroll
    for (int kk = 0; kk < KCH; kk++) {
        float4 w = wp[(size_t)kk * 256];
        #pragma unroll
        for (int j = 0; j < BG; j++) {
            float h = hs[j][kk];
            acc[j].x = fmaf(h, w.x, acc[j].x);
            acc[j].y = fmaf(h, w.y, acc[j].y);
            acc[j].z = fmaf(h, w.z, acc[j].z);
            acc[j].w = fmaf(h, w.w, acc[j].w);
        }
    }
    float4* qp = reinterpret_cast<float4*>(g_qpart);
    #pragma unroll
    for (int j = 0; j < BG; j++)
        qp[((size_t)blockIdx.y * B + bg * BG + j) * 256 + tid] = acc[j];
}

// ---------------------------------------------------------------------------
// Kernel 1b: q = sum over KSLICES partials. grid (128), 256 threads.
// ---------------------------------------------------------------------------
__global__ __launch_bounds__(256) void qreduce_kernel()
{
    const int idx = blockIdx.x * 256 + threadIdx.x;
    float v = 0.f;
    #pragma unroll
    for (int p = 0; p < KSLICES; p++)
        v += g_qpart[(size_t)p * (B * H) + idx];
    g_q[idx] = v;
}

// ---------------------------------------------------------------------------
// Kernel 2: warp-autonomous split, SOFTWARE-PIPELINED one row ahead.
// grid (NSPLIT, B), 128 threads. Warp owns RPW=32 full rows; no barriers
// in the main loop. Prefetch row r+1 while computing row r.
// ---------------------------------------------------------------------------
__global__ void __launch_bounds__(128, 4) split_kernel(const float* __restrict__ cntx)
{
    __shared__ float  q_s[H];              // 4 KB
    __shared__ float4 accbuf[WARPS][256];  // 16 KB
    __shared__ float  mlbuf[WARPS][2];

    const int tid  = threadIdx.x;
    const int wid  = tid >> 5;
    const int lane = tid & 31;
    const int b    = blockIdx.y;
    const int sp   = blockIdx.x;

    float4* q_s4 = reinterpret_cast<float4*>(q_s);
    q_s4[tid]       = reinterpret_cast<const float4*>(g_q)[b * 256 + tid];
    q_s4[tid + 128] = reinterpret_cast<const float4*>(g_q)[b * 256 + tid + 128];
    __syncthreads();

    const float4* base4 = reinterpret_cast<const float4*>(
        cntx + ((size_t)b * S + (size_t)sp * CH) * H)
        + (size_t)(wid * RPW) * 256 + lane;

    float m = -1e30f, l = 0.f;
    float4 acc[8];
    #pragma unroll
    for (int j = 0; j < 8; j++) acc[j] = make_float4(0.f, 0.f, 0.f, 0.f);

    // prologue: load row 0
    float4 vn[8];
    #pragma unroll
    for (int j = 0; j < 8; j++) vn[j] = __ldcs(&base4[j * 32]);

    for (int r = 0; r < RPW; r++) {
        float4 v[8];
        #pragma unroll
        for (int j = 0; j < 8; j++) v[j] = vn[j];

        // prefetch next row (overlaps with everything below)
        if (r + 1 < RPW) {
            const float4* nx = base4 + (size_t)(r + 1) * 256;
            #pragma unroll
            for (int j = 0; j < 8; j++) vn[j] = __ldcs(&nx[j * 32]);
        }

        // dot with q
        float d = 0.f;
        #pragma unroll
        for (int j = 0; j < 8; j++) {
            float4 qv = q_s4[j * 32 + lane];
            d = fmaf(v[j].x, qv.x, d);
            d = fmaf(v[j].y, qv.y, d);
            d = fmaf(v[j].z, qv.z, d);
            d = fmaf(v[j].w, qv.w, d);
        }
        #pragma unroll
        for (int off = 16; off > 0; off >>= 1)
            d += __shfl_xor_sync(0xffffffffu, d, off);

        // online softmax (warp-uniform)
        float mnew = fmaxf(m, d);
        float corr = __expf(m - mnew);
        float e    = __expf(d - mnew);
        l = fmaf(l, corr, e);
        #pragma unroll
        for (int j = 0; j < 8; j++) {
            acc[j].x = fmaf(acc[j].x, corr, e * v[j].x);
            acc[j].y = fmaf(acc[j].y, corr, e * v[j].y);
            acc[j].z = fmaf(acc[j].z, corr, e * v[j].z);
            acc[j].w = fmaf(acc[j].w, corr, e * v[j].w);
        }
        m = mnew;
    }

    // ---- CTA merge of 4 warp states ----
    if (lane == 0) { mlbuf[wid][0] = m; mlbuf[wid][1] = l; }
    __syncthreads();

    float M = -1e30f;
    #pragma unroll
    for (int w = 0; w < WARPS; w++) M = fmaxf(M, mlbuf[w][0]);
    float L = 0.f;
    #pragma unroll
    for (int w = 0; w < WARPS; w++) L += mlbuf[w][1] * __expf(mlbuf[w][0] - M);

    float wi = __expf(m - M);   // this warp's rescale
    #pragma unroll
    for (int j = 0; j < 8; j++) {
        float4 a = acc[j];
        a.x *= wi; a.y *= wi; a.z *= wi; a.w *= wi;
        accbuf[wid][j * 32 + lane] = a;
    }
    __syncthreads();

    #pragma unroll
    for (int c0 = 0; c0 < 2; c0++) {
        int c = tid + c0 * 128;
        float4 s = accbuf[0][c];
        #pragma unroll
        for (int w = 1; w < WARPS; w++) {
            float4 p = accbuf[w][c];
            s.x += p.x; s.y += p.y; s.z += p.z; s.w += p.w;
        }
        g_pacc[((size_t)b * NSPLIT + sp) * 256 + c] = s;
    }
    if (tid == 0) {
        g_ml[(b * NSPLIT + sp) * 2 + 0] = M;
        g_ml[(b * NSPLIT + sp) * 2 + 1] = L;
    }
}

// ---------------------------------------------------------------------------
// Kernel 3: combine. grid (8, B), 256 threads.
// g_ml staged in SMEM (no serial L2 chains). CTA covers 32 float4 cols;
// 8 groups of 32 threads handle 2 splits each; smem reduce.
// ---------------------------------------------------------------------------
__global__ __launch_bounds__(256) void combine_kernel(const float* __restrict__ h_t,
                                                      const float* __restrict__ alpha,
                                                      const float* __restrict__ beta,
                                                      float* __restrict__ out)
{
    __shared__ float  ml[NSPLIT * 2];
    __shared__ float4 red[8][32];

    const int tid = threadIdx.x;
    const int c   = tid & 31;              // col within chunk
    const int grp = tid >> 5;              // 0..7
    const int col = blockIdx.x * 32 + c;   // float4 column 0..255
    const int b   = blockIdx.y;

    if (tid < NSPLIT * 2) ml[tid] = g_ml[b * NSPLIT * 2 + tid];
    __syncthreads();

    float M = -1e30f;
    #pragma unroll
    for (int i = 0; i < NSPLIT; i++) M = fmaxf(M, ml[i * 2]);
    float L = 0.f;
    #pragma unroll
    for (int i = 0; i < NSPLIT; i++) L += ml[i * 2 + 1] * __expf(ml[i * 2] - M);

    float4 o = make_float4(0.f, 0.f, 0.f, 0.f);
    #pragma unroll
    for (int j = 0; j < 2; j++) {
        int i = grp * 2 + j;
        float wi = __expf(ml[i * 2] - M);
        float4 p = g_pacc[((size_t)b * NSPLIT + i) * 256 + col];
        o.x = fmaf(wi, p.x, o.x);
        o.y = fmaf(wi, p.y, o.y);
        o.z = fmaf(wi, p.z, o.z);
        o.w = fmaf(wi, p.w, o.w);
    }
    red[grp][c] = o;
    __syncthreads();

    if (grp == 0) {
        #pragma unroll
        for (int w = 1; w < 8; w++) {
            float4 p = red[w][c];
            o.x += p.x; o.y += p.y; o.z += p.z; o.w += p.w;
        }
        float a  = alpha[0];
        float bt = beta[0] / L;
        float4 hv = reinterpret_cast<const float4*>(h_t)[b * 256 + col];
        float4 res;
        res.x = fmaf(a, hv.x, bt * o.x);
        res.y = fmaf(a, hv.y, bt * o.y);
        res.z = fmaf(a, hv.z, bt * o.z);
        res.w = fmaf(a, hv.w, bt * o.w);
        reinterpret_cast<float4*>(out)[b * 256 + col] = res;
    }
}

// ---------------------------------------------------------------------------
extern "C" void kernel_launch(void* const* d_in, const int* in_sizes, int n_in,
                              void* d_out, int out_size)
{
    const float* h_t   = (const float*)d_in[0];
    const float* cntx  = (const float*)d_in[1];
    const float* W     = (const float*)d_in[2];
    const float* alpha = (const float*)d_in[3];
    const float* beta  = (const float*)d_in[4];
    float* out = (float*)d_out;

    qpart_kernel<<<dim3(1, KSLICES, B / BG), 256>>>(h_t, W);
    qreduce_kernel<<<B * H / 256, 256>>>();
    split_kernel<<<dim3(NSPLIT, B), 128>>>(cntx);
    combine_kernel<<<dim3(8, B), 256>>>(h_t, alpha, beta, out);
}